// round 1
// baseline (speedup 1.0000x reference)
#include <cuda_runtime.h>

// Problem constants (FiBiNet): B=1024, F=32, D=64, g=2
// P = 496 pairs, emb = 2048, red = 32, OUT = 512, out row = 2560
static constexpr int Bn   = 1024;
static constexpr int Fn   = 32;
static constexpr int Dn   = 64;
static constexpr int Pn   = 496;
static constexpr int EMB  = 2048;   // F*D
static constexpr int REDn = 32;
static constexpr int ZDIM = 128;    // F*2*g
static constexpr int OUTN = 512;
static constexpr int OROW = 2560;   // EMB + OUTN

// Scratch for pair dots (B x P). Static __device__ array: allocation-guard safe.
__device__ float g_dots[Bn * Pn];

// ---------------------------------------------------------------------------
// Kernel 1: SENet branch + LayerNorm -> out[:, 0:2048]
// One block per batch row. 256 threads.
// ---------------------------------------------------------------------------
__global__ __launch_bounds__(256) void senet_kernel(
    const float* __restrict__ x,  const float* __restrict__ W1, const float* __restrict__ b1,
    const float* __restrict__ W2, const float* __restrict__ b2,
    const float* __restrict__ ln_s, const float* __restrict__ ln_b,
    float* __restrict__ out)
{
    const int b = blockIdx.x;
    const int t = threadIdx.x;

    __shared__ float sx[EMB];
    __shared__ float sz[ZDIM];
    __shared__ float sa1[REDn];
    __shared__ float warp_sum[8], warp_sq[8];

    const float* xrow = x + (size_t)b * EMB;

    // Load x row (2048 floats) via float4
    #pragma unroll
    for (int r = 0; r < 2; r++) {
        int idx = t + 256 * r;
        ((float4*)sx)[idx] = ((const float4*)xrow)[idx];
    }
    __syncthreads();

    // z: per (feature f, group gi): max and mean over 32 contiguous elems.
    // Layout after reshape: z[f*4 + gi] = max, z[f*4 + 2 + gi] = mean.
    if (t < 64) {
        const int f = t >> 1, gi = t & 1;
        const float* base = sx + f * 64 + gi * 32;
        float mx = base[0], sm = base[0];
        #pragma unroll
        for (int k = 1; k < 32; k++) {
            float v = base[k];
            mx = fmaxf(mx, v);
            sm += v;
        }
        sz[f * 4 + gi]     = mx;
        sz[f * 4 + 2 + gi] = sm * (1.0f / 32.0f);
    }
    __syncthreads();

    // a1 = relu(z @ W1 + b1), W1 is (128, 32) row-major
    if (t < REDn) {
        float acc = b1[t];
        #pragma unroll 4
        for (int k = 0; k < ZDIM; k++) acc += sz[k] * W1[k * REDn + t];
        sa1[t] = fmaxf(acc, 0.0f);
    }
    __syncthreads();

    // weights = a1 @ W2 + b2 ; senet = x*(1+weights); accumulate LN stats
    float sv[8];
    float sum = 0.f, sq = 0.f;
    #pragma unroll
    for (int r = 0; r < 8; r++) {
        const int j = t + 256 * r;
        float w = b2[j];
        #pragma unroll 8
        for (int k = 0; k < REDn; k++) w += sa1[k] * W2[k * EMB + j];
        float s = sx[j] * (1.0f + w);
        sv[r] = s;
        sum += s;
        sq  += s * s;
    }
    // block reduction (8 warps)
    #pragma unroll
    for (int off = 16; off; off >>= 1) {
        sum += __shfl_xor_sync(0xffffffffu, sum, off);
        sq  += __shfl_xor_sync(0xffffffffu, sq,  off);
    }
    if ((t & 31) == 0) { warp_sum[t >> 5] = sum; warp_sq[t >> 5] = sq; }
    __syncthreads();
    sum = 0.f; sq = 0.f;
    #pragma unroll
    for (int wv = 0; wv < 8; wv++) { sum += warp_sum[wv]; sq += warp_sq[wv]; }

    const float mu   = sum * (1.0f / EMB);
    const float var  = sq * (1.0f / EMB) - mu * mu;
    const float rstd = rsqrtf(var + 1e-6f);

    float* orow = out + (size_t)b * OROW;
    #pragma unroll
    for (int r = 0; r < 8; r++) {
        const int j = t + 256 * r;
        orow[j] = (sv[r] - mu) * rstd * ln_s[j] + ln_b[j];
    }
}

// ---------------------------------------------------------------------------
// Kernel 2: pairwise bilinear dots.
// dots[b,p] = (x[b,i] @ Wp[p] + bp[p]) . x[b,j]
// Grid: (496 pairs, 4 batch quarters). Block 256 threads.
// Each thread: 4 batches x 4 output cols register tile (16 FFMA per W float4).
// ---------------------------------------------------------------------------
__global__ __launch_bounds__(256) void pair_dots_kernel(
    const float* __restrict__ x, const float* __restrict__ Wp, const float* __restrict__ bp)
{
    const int p = blockIdx.x;

    // pair index p -> (i, j), lexicographic combinations of range(32)
    int i = 0, rem = p;
    while (rem >= (Fn - 1) - i) { rem -= (Fn - 1) - i; ++i; }
    const int j = i + 1 + rem;

    __shared__ float sW[64 * 64];      // Wp[p], row d contiguous in e
    __shared__ float sXi[64][68];      // [batch][d], pad 68 (16B-aligned rows)

    // Load Wp[p] (16 KB) once
    const float* wsrc = Wp + (size_t)p * 4096;
    #pragma unroll
    for (int r = 0; r < 4; r++) {
        int idx = threadIdx.x + 256 * r;
        ((float4*)sW)[idx] = ((const float4*)wsrc)[idx];
    }

    const int c  = threadIdx.x & 15;   // e-chunk (4 cols)
    const int q  = threadIdx.x >> 4;   // batch quad
    const int e0 = c * 4;
    const int bq = q * 4;

    const float4 bpv = *(const float4*)(bp + (size_t)p * 64 + e0);

    const int bt_base = blockIdx.y * 256;

    for (int bt = 0; bt < 4; bt++) {
        const int b0 = bt_base + bt * 64;

        __syncthreads();   // previous tile consumed (also guards sW on bt==0)
        // Load xi tile: 64 batches x 64 d
        #pragma unroll
        for (int r = 0; r < 4; r++) {
            int idx = threadIdx.x + 256 * r;
            int bb = idx >> 4, cc = idx & 15;
            float4 v = *(const float4*)(x + (size_t)(b0 + bb) * EMB + i * 64 + cc * 4);
            *(float4*)&sXi[bb][cc * 4] = v;
        }
        __syncthreads();

        float acc[4][4];
        #pragma unroll
        for (int a = 0; a < 4; a++)
            #pragma unroll
            for (int e = 0; e < 4; e++) acc[a][e] = 0.f;

        #pragma unroll 8
        for (int d = 0; d < 64; d++) {
            const float4 w = *(const float4*)&sW[d * 64 + e0];
            const float xi0 = sXi[bq + 0][d];
            const float xi1 = sXi[bq + 1][d];
            const float xi2 = sXi[bq + 2][d];
            const float xi3 = sXi[bq + 3][d];
            acc[0][0] += xi0 * w.x; acc[0][1] += xi0 * w.y; acc[0][2] += xi0 * w.z; acc[0][3] += xi0 * w.w;
            acc[1][0] += xi1 * w.x; acc[1][1] += xi1 * w.y; acc[1][2] += xi1 * w.z; acc[1][3] += xi1 * w.w;
            acc[2][0] += xi2 * w.x; acc[2][1] += xi2 * w.y; acc[2][2] += xi2 * w.z; acc[2][3] += xi2 * w.w;
            acc[3][0] += xi3 * w.x; acc[3][1] += xi3 * w.y; acc[3][2] += xi3 * w.z; acc[3][3] += xi3 * w.w;
        }

        // epilogue: dot with xj (+ bp folded here), reduce over 16 e-chunks
        float part[4];
        #pragma unroll
        for (int bi = 0; bi < 4; bi++) {
            const float4 xj = *(const float4*)(x + (size_t)(b0 + bq + bi) * EMB + j * 64 + e0);
            part[bi] = (acc[bi][0] + bpv.x) * xj.x + (acc[bi][1] + bpv.y) * xj.y
                     + (acc[bi][2] + bpv.z) * xj.z + (acc[bi][3] + bpv.w) * xj.w;
        }
        #pragma unroll
        for (int bi = 0; bi < 4; bi++) {
            #pragma unroll
            for (int off = 8; off; off >>= 1)
                part[bi] += __shfl_xor_sync(0xffffffffu, part[bi], off, 16);
        }
        if (c == 0) {
            #pragma unroll
            for (int bi = 0; bi < 4; bi++)
                g_dots[(size_t)(b0 + bq + bi) * Pn + p] = part[bi];
        }
    }
}

// ---------------------------------------------------------------------------
// Kernel 3: bilinear = dots @ Wo + bo -> out[:, 2048:2560]
// Tiled GEMM: M=1024, N=512, K=496. BM=BN=64, BK=16, 4x4 thread tile.
// ---------------------------------------------------------------------------
__global__ __launch_bounds__(256) void outgemm_kernel(
    const float* __restrict__ Wo, const float* __restrict__ bo, float* __restrict__ out)
{
    const int n0 = blockIdx.x * 64;
    const int m0 = blockIdx.y * 64;

    __shared__ float sA[16][64];   // [k][m]
    __shared__ float sB[16][64];   // [k][n]

    const int tx = threadIdx.x & 15;   // n chunk
    const int ty = threadIdx.x >> 4;   // m chunk

    float acc[4][4];
    #pragma unroll
    for (int mi = 0; mi < 4; mi++)
        #pragma unroll
        for (int ni = 0; ni < 4; ni++) acc[mi][ni] = 0.f;

    for (int k0 = 0; k0 < Pn; k0 += 16) {
        __syncthreads();
        {   // A tile: dots[m0+m][k0+k], stored transposed
            const int m = threadIdx.x >> 2, kc = threadIdx.x & 3;
            float4 v = *(const float4*)(g_dots + (size_t)(m0 + m) * Pn + k0 + kc * 4);
            sA[kc * 4 + 0][m] = v.x;
            sA[kc * 4 + 1][m] = v.y;
            sA[kc * 4 + 2][m] = v.z;
            sA[kc * 4 + 3][m] = v.w;
        }
        {   // B tile: Wo[k0+k][n0+n]
            const int k = threadIdx.x >> 4, nc = threadIdx.x & 15;
            *(float4*)&sB[k][nc * 4] =
                *(const float4*)(Wo + (size_t)(k0 + k) * OUTN + n0 + nc * 4);
        }
        __syncthreads();

        #pragma unroll
        for (int k = 0; k < 16; k++) {
            const float4 a  = *(const float4*)&sA[k][ty * 4];
            const float4 bv = *(const float4*)&sB[k][tx * 4];
            acc[0][0] += a.x * bv.x; acc[0][1] += a.x * bv.y; acc[0][2] += a.x * bv.z; acc[0][3] += a.x * bv.w;
            acc[1][0] += a.y * bv.x; acc[1][1] += a.y * bv.y; acc[1][2] += a.y * bv.z; acc[1][3] += a.y * bv.w;
            acc[2][0] += a.z * bv.x; acc[2][1] += a.z * bv.y; acc[2][2] += a.z * bv.z; acc[2][3] += a.z * bv.w;
            acc[3][0] += a.w * bv.x; acc[3][1] += a.w * bv.y; acc[3][2] += a.w * bv.z; acc[3][3] += a.w * bv.w;
        }
    }

    #pragma unroll
    for (int mi = 0; mi < 4; mi++) {
        const int m = m0 + ty * 4 + mi;
        float* orow = out + (size_t)m * OROW + EMB + n0;
        #pragma unroll
        for (int ni = 0; ni < 4; ni++) {
            const int n = tx * 4 + ni;
            orow[n] = acc[mi][ni] + bo[n0 + n];
        }
    }
}

// ---------------------------------------------------------------------------
extern "C" void kernel_launch(void* const* d_in, const int* in_sizes, int n_in,
                              void* d_out, int out_size)
{
    const float* x    = (const float*)d_in[0];
    const float* W1   = (const float*)d_in[1];
    const float* b1   = (const float*)d_in[2];
    const float* W2   = (const float*)d_in[3];
    const float* b2   = (const float*)d_in[4];
    const float* ln_s = (const float*)d_in[5];
    const float* ln_b = (const float*)d_in[6];
    const float* Wp   = (const float*)d_in[7];
    const float* bp   = (const float*)d_in[8];
    const float* Wo   = (const float*)d_in[9];
    const float* bo   = (const float*)d_in[10];
    float* out = (float*)d_out;

    senet_kernel<<<Bn, 256>>>(x, W1, b1, W2, b2, ln_s, ln_b, out);
    pair_dots_kernel<<<dim3(Pn, 4), 256>>>(x, Wp, bp);
    outgemm_kernel<<<dim3(OUTN / 64, Bn / 64), 256>>>(Wo, bo, out);
}

// round 3
// speedup vs baseline: 1.4849x; 1.4849x over previous
#include <cuda_runtime.h>
#include <cuda_bf16.h>
#include <cstdint>

// Problem constants (FiBiNet): B=1024, F=32, D=64, g=2
static constexpr int Bn   = 1024;
static constexpr int Pn   = 496;
static constexpr int EMB  = 2048;   // F*D
static constexpr int OUTN = 512;
static constexpr int OROW = 2560;   // EMB + OUTN

// Scratch (static __device__: allocation-guard safe)
__device__ float g_dots[Pn * Bn];   // [p][b]  (coalesced stores + outgemm loads)
__device__ float g_a1[Bn * 32];

// ---------------------------------------------------------------------------
// HMMA: D(16x8,f32) += A(16x16,bf16 row) x B(16x8,bf16 col)
// ---------------------------------------------------------------------------
__device__ __forceinline__ void mma16816(float* d, const uint32_t* a, const uint32_t* b) {
    asm volatile(
        "mma.sync.aligned.m16n8k16.row.col.f32.bf16.bf16.f32 "
        "{%0,%1,%2,%3}, {%4,%5,%6,%7}, {%8,%9}, {%0,%1,%2,%3};"
        : "+f"(d[0]), "+f"(d[1]), "+f"(d[2]), "+f"(d[3])
        : "r"(a[0]), "r"(a[1]), "r"(a[2]), "r"(a[3]), "r"(b[0]), "r"(b[1]));
}

// ---------------------------------------------------------------------------
// Kernel A: a1 = relu(z @ W1 + b1). 8 warps/block, 1 batch row per warp.
// ---------------------------------------------------------------------------
__global__ __launch_bounds__(256) void senet_a1_kernel(
    const float* __restrict__ x, const float* __restrict__ W1, const float* __restrict__ b1)
{
    __shared__ float sW1[128 * 32];
    __shared__ float sz[8][128];

    const int t = threadIdx.x, w = t >> 5, lane = t & 31;
    const int row = blockIdx.x * 8 + w;

    #pragma unroll
    for (int r = 0; r < 4; r++)
        ((float4*)sW1)[t + 256 * r] = ((const float4*)W1)[t + 256 * r];
    __syncthreads();

    const float* xrow = x + (size_t)row * EMB;
    #pragma unroll
    for (int half = 0; half < 2; half++) {
        const int s = lane + 32 * half;       // 32-elem segment: f = s>>1, group = s&1
        const float* base = xrow + s * 32;
        float mx = -1e30f, sm = 0.f;
        #pragma unroll
        for (int it = 0; it < 8; it++) {
            float4 v = *(const float4*)(base + it * 4);
            mx = fmaxf(mx, fmaxf(fmaxf(v.x, v.y), fmaxf(v.z, v.w)));
            sm += v.x + v.y + v.z + v.w;
        }
        const int f = s >> 1, gi = s & 1;
        sz[w][f * 4 + gi]     = mx;              // max slots
        sz[w][f * 4 + 2 + gi] = sm * (1.0f / 32.0f);  // mean slots
    }
    __syncwarp();

    float acc = b1[lane];
    #pragma unroll 8
    for (int k = 0; k < 128; k++) acc += sz[w][k] * sW1[k * 32 + lane];
    g_a1[row * 32 + lane] = fmaxf(acc, 0.0f);
}

// ---------------------------------------------------------------------------
// Kernel B: weights = a1@W2+b2; senet = x*(1+w); LayerNorm -> out[:,0:2048]
// 8 rows/block, 256 threads, 8x8 register outer product over k=32.
// ---------------------------------------------------------------------------
__global__ __launch_bounds__(256) void senet_ln_kernel(
    const float* __restrict__ x, const float* __restrict__ W2, const float* __restrict__ b2,
    const float* __restrict__ ln_s, const float* __restrict__ ln_b, float* __restrict__ out)
{
    __shared__ float sa1[8 * 32];
    __shared__ float wsum[8][8], wsq[8][8];
    __shared__ float mu_s[8], rs_s[8];

    const int t = threadIdx.x;
    const int row0 = blockIdx.x * 8;

    sa1[t] = g_a1[row0 * 32 + t];
    __syncthreads();

    float acc[8][8];
    #pragma unroll
    for (int c = 0; c < 8; c++)
        #pragma unroll
        for (int r = 0; r < 8; r++) acc[c][r] = 0.f;

    #pragma unroll 4
    for (int k = 0; k < 32; k++) {
        float w2v[8], a1v[8];
        #pragma unroll
        for (int c = 0; c < 8; c++) w2v[c] = W2[k * EMB + t + 256 * c];
        #pragma unroll
        for (int r = 0; r < 8; r++) a1v[r] = sa1[r * 32 + k];
        #pragma unroll
        for (int c = 0; c < 8; c++)
            #pragma unroll
            for (int r = 0; r < 8; r++) acc[c][r] += a1v[r] * w2v[c];
    }

    float sum[8], sq[8];
    #pragma unroll
    for (int r = 0; r < 8; r++) { sum[r] = 0.f; sq[r] = 0.f; }
    #pragma unroll
    for (int c = 0; c < 8; c++) {
        const int j = t + 256 * c;
        const float b2v = b2[j];
        #pragma unroll
        for (int r = 0; r < 8; r++) {
            float xv = x[(size_t)(row0 + r) * EMB + j];
            float s = xv * (1.0f + b2v + acc[c][r]);
            acc[c][r] = s;
            sum[r] += s;
            sq[r]  += s * s;
        }
    }
    const int w = t >> 5, lane = t & 31;
    #pragma unroll
    for (int r = 0; r < 8; r++) {
        float a = sum[r], b = sq[r];
        #pragma unroll
        for (int off = 16; off; off >>= 1) {
            a += __shfl_xor_sync(0xffffffffu, a, off);
            b += __shfl_xor_sync(0xffffffffu, b, off);
        }
        if (lane == 0) { wsum[w][r] = a; wsq[w][r] = b; }
    }
    __syncthreads();
    if (t < 8) {
        float a = 0.f, b = 0.f;
        #pragma unroll
        for (int ww = 0; ww < 8; ww++) { a += wsum[ww][t]; b += wsq[ww][t]; }
        const float mu = a * (1.0f / EMB);
        mu_s[t] = mu;
        rs_s[t] = rsqrtf(b * (1.0f / EMB) - mu * mu + 1e-6f);
    }
    __syncthreads();

    #pragma unroll
    for (int c = 0; c < 8; c++) {
        const int j = t + 256 * c;
        const float lsv = ln_s[j], lbv = ln_b[j];
        #pragma unroll
        for (int r = 0; r < 8; r++)
            out[(size_t)(row0 + r) * OROW + j] = (acc[c][r] - mu_s[r]) * rs_s[r] * lsv + lbv;
    }
}

// ---------------------------------------------------------------------------
// Kernel 2: pairwise bilinear dots via HMMA bf16 split-precision.
// Block = (pair p, batch tile of 128). 8 warps, warp w owns rows w*16..w*16+15.
// proj(128x64) = xi @ Wp[p] via mma.m16n8k16 (hi*hi + hi*lo + lo*hi);
// dots[b] = sum_e (proj+bp) * xj  -> g_dots[p][b]
// ---------------------------------------------------------------------------
static constexpr int XPAD = 72;   // bf16 row stride for xi tiles (4-bank row skew)
static constexpr int WPAD = 72;   // bf16 row stride for W^T tiles
static constexpr int JPAD = 68;   // f32 row stride for xj tile (16B-aligned rows)

static constexpr int SM_XH = 0;
static constexpr int SM_XL = SM_XH + 128 * XPAD;              // bf16 counts
static constexpr int SM_WH = SM_XL + 128 * XPAD;
static constexpr int SM_WL = SM_WH + 64 * WPAD;
static constexpr int SM_END_BF16 = SM_WL + 64 * WPAD;
static constexpr int SM_XJ_BYTES = SM_END_BF16 * 2;           // float region starts here
static constexpr int SM_BP_BYTES = SM_XJ_BYTES + 128 * JPAD * 4;
static constexpr int PAIR_SMEM   = SM_BP_BYTES + 64 * 4;

__global__ __launch_bounds__(256) void pair_mma_kernel(
    const float* __restrict__ x, const float* __restrict__ Wp, const float* __restrict__ bp)
{
    extern __shared__ char smem[];
    __nv_bfloat16* sXh = (__nv_bfloat16*)smem;
    __nv_bfloat16* sXl = sXh + 128 * XPAD;
    __nv_bfloat16* sWh = sXh + SM_WH;
    __nv_bfloat16* sWl = sXh + SM_WL;
    float* sXj = (float*)(smem + SM_XJ_BYTES);
    float* sbp = (float*)(smem + SM_BP_BYTES);

    const int t = threadIdx.x, wid = t >> 5, lane = t & 31;
    const int p = blockIdx.x;
    const int b0 = blockIdx.y * 128;

    // pair p -> (i, j)
    int i = 0, rem = p;
    while (rem >= 31 - i) { rem -= 31 - i; ++i; }
    const int j = i + 1 + rem;

    if (t < 64) sbp[t] = bp[p * 64 + t];

    // --- Wp[p] (64x64) -> transposed bf16 hi/lo: sW[e][d] ---
    #pragma unroll
    for (int it = 0; it < 16; it++) {
        const int idx = t + 256 * it;
        const int d = idx >> 6, e = idx & 63;
        const float v = Wp[(size_t)p * 4096 + idx];
        const __nv_bfloat16 h = __float2bfloat16(v);
        sWh[e * WPAD + d] = h;
        sWl[e * WPAD + d] = __float2bfloat16(v - __bfloat162float(h));
    }

    // --- xi tile (128x64) -> bf16 hi/lo; xj tile -> f32 ---
    #pragma unroll
    for (int it = 0; it < 8; it++) {
        const int idx = t + 256 * it;
        const int row = idx >> 4, ch = idx & 15;
        const float4 v = *(const float4*)(x + (size_t)(b0 + row) * EMB + i * 64 + ch * 4);
        __nv_bfloat16 h0 = __float2bfloat16(v.x), h1 = __float2bfloat16(v.y);
        __nv_bfloat16 h2 = __float2bfloat16(v.z), h3 = __float2bfloat16(v.w);
        __nv_bfloat162 hA = __halves2bfloat162(h0, h1), hB = __halves2bfloat162(h2, h3);
        __nv_bfloat162 lA = __halves2bfloat162(__float2bfloat16(v.x - __bfloat162float(h0)),
                                               __float2bfloat16(v.y - __bfloat162float(h1)));
        __nv_bfloat162 lB = __halves2bfloat162(__float2bfloat16(v.z - __bfloat162float(h2)),
                                               __float2bfloat16(v.w - __bfloat162float(h3)));
        uint2 hp, lp;
        hp.x = *(uint32_t*)&hA; hp.y = *(uint32_t*)&hB;
        lp.x = *(uint32_t*)&lA; lp.y = *(uint32_t*)&lB;
        *(uint2*)(sXh + row * XPAD + ch * 4) = hp;
        *(uint2*)(sXl + row * XPAD + ch * 4) = lp;

        const float4 vj = *(const float4*)(x + (size_t)(b0 + row) * EMB + j * 64 + ch * 4);
        *(float4*)(sXj + row * JPAD + ch * 4) = vj;
    }
    __syncthreads();

    // --- MMA mainloop ---
    const int r = lane >> 2;            // row within 8-row group
    const int kq = (lane & 3) * 2;      // k offset within 16-k tile

    // Preload A fragments for all 4 k-tiles (hi and lo)
    uint32_t ah[4][4], al[4][4];
    const int m0 = wid * 16;
    #pragma unroll
    for (int kt = 0; kt < 4; kt++) {
        const int kb = kt * 16 + kq;
        ah[kt][0] = *(const uint32_t*)(sXh + (m0 + r) * XPAD + kb);
        ah[kt][1] = *(const uint32_t*)(sXh + (m0 + r + 8) * XPAD + kb);
        ah[kt][2] = *(const uint32_t*)(sXh + (m0 + r) * XPAD + kb + 8);
        ah[kt][3] = *(const uint32_t*)(sXh + (m0 + r + 8) * XPAD + kb + 8);
        al[kt][0] = *(const uint32_t*)(sXl + (m0 + r) * XPAD + kb);
        al[kt][1] = *(const uint32_t*)(sXl + (m0 + r + 8) * XPAD + kb);
        al[kt][2] = *(const uint32_t*)(sXl + (m0 + r) * XPAD + kb + 8);
        al[kt][3] = *(const uint32_t*)(sXl + (m0 + r + 8) * XPAD + kb + 8);
    }

    float acc[8][4];
    #pragma unroll
    for (int nt = 0; nt < 8; nt++)
        #pragma unroll
        for (int q = 0; q < 4; q++) acc[nt][q] = 0.f;

    #pragma unroll
    for (int nt = 0; nt < 8; nt++) {
        const int nrow = nt * 8 + r;    // B fragment column index = e
        #pragma unroll
        for (int kt = 0; kt < 4; kt++) {
            const int kb = kt * 16 + kq;
            uint32_t bh[2], bl[2];
            bh[0] = *(const uint32_t*)(sWh + nrow * WPAD + kb);
            bh[1] = *(const uint32_t*)(sWh + nrow * WPAD + kb + 8);
            bl[0] = *(const uint32_t*)(sWl + nrow * WPAD + kb);
            bl[1] = *(const uint32_t*)(sWl + nrow * WPAD + kb + 8);
            mma16816(acc[nt], ah[kt], bh);
            mma16816(acc[nt], ah[kt], bl);
            mma16816(acc[nt], al[kt], bh);
        }
    }

    // --- epilogue: dots = sum_e (proj + bp[e]) * xj[.,e], quad reduction ---
    float dot0 = 0.f, dot1 = 0.f;
    #pragma unroll
    for (int nt = 0; nt < 8; nt++) {
        const int c0 = nt * 8 + (lane & 3) * 2;
        const float bp0 = sbp[c0], bp1 = sbp[c0 + 1];
        const float2 xj0 = *(const float2*)(sXj + (m0 + r) * JPAD + c0);
        const float2 xj1 = *(const float2*)(sXj + (m0 + r + 8) * JPAD + c0);
        dot0 += (acc[nt][0] + bp0) * xj0.x + (acc[nt][1] + bp1) * xj0.y;
        dot1 += (acc[nt][2] + bp0) * xj1.x + (acc[nt][3] + bp1) * xj1.y;
    }
    dot0 += __shfl_xor_sync(0xffffffffu, dot0, 1);
    dot0 += __shfl_xor_sync(0xffffffffu, dot0, 2);
    dot1 += __shfl_xor_sync(0xffffffffu, dot1, 1);
    dot1 += __shfl_xor_sync(0xffffffffu, dot1, 2);
    if ((lane & 3) == 0) {
        g_dots[(size_t)p * Bn + b0 + m0 + r]     = dot0;
        g_dots[(size_t)p * Bn + b0 + m0 + r + 8] = dot1;
    }
}

// ---------------------------------------------------------------------------
// Kernel 3: bilinear = dots @ Wo + bo -> out[:, 2048:2560]
// dots stored [p][b]. M=1024, N=512, K=496.
// ---------------------------------------------------------------------------
__global__ __launch_bounds__(256) void outgemm_kernel(
    const float* __restrict__ Wo, const float* __restrict__ bo, float* __restrict__ out)
{
    const int n0 = blockIdx.x * 64;
    const int m0 = blockIdx.y * 64;

    __shared__ float sA[16][64];   // [k][m]
    __shared__ float sB[16][64];   // [k][n]

    const int tx = threadIdx.x & 15;
    const int ty = threadIdx.x >> 4;

    float acc[4][4];
    #pragma unroll
    for (int mi = 0; mi < 4; mi++)
        #pragma unroll
        for (int ni = 0; ni < 4; ni++) acc[mi][ni] = 0.f;

    for (int k0 = 0; k0 < Pn; k0 += 16) {
        __syncthreads();
        {   // A tile: dots[k0+k][m0+m] — already [k][m]
            const int k = threadIdx.x >> 4, mc = threadIdx.x & 15;
            *(float4*)&sA[k][mc * 4] =
                *(const float4*)(g_dots + (size_t)(k0 + k) * Bn + m0 + mc * 4);
        }
        {   // B tile: Wo[k0+k][n0+n]
            const int k = threadIdx.x >> 4, nc = threadIdx.x & 15;
            *(float4*)&sB[k][nc * 4] =
                *(const float4*)(Wo + (size_t)(k0 + k) * OUTN + n0 + nc * 4);
        }
        __syncthreads();

        #pragma unroll
        for (int k = 0; k < 16; k++) {
            const float4 a  = *(const float4*)&sA[k][ty * 4];
            const float4 bv = *(const float4*)&sB[k][tx * 4];
            acc[0][0] += a.x * bv.x; acc[0][1] += a.x * bv.y; acc[0][2] += a.x * bv.z; acc[0][3] += a.x * bv.w;
            acc[1][0] += a.y * bv.x; acc[1][1] += a.y * bv.y; acc[1][2] += a.y * bv.z; acc[1][3] += a.y * bv.w;
            acc[2][0] += a.z * bv.x; acc[2][1] += a.z * bv.y; acc[2][2] += a.z * bv.z; acc[2][3] += a.z * bv.w;
            acc[3][0] += a.w * bv.x; acc[3][1] += a.w * bv.y; acc[3][2] += a.w * bv.z; acc[3][3] += a.w * bv.w;
        }
    }

    #pragma unroll
    for (int mi = 0; mi < 4; mi++) {
        const int m = m0 + ty * 4 + mi;
        float* orow = out + (size_t)m * OROW + EMB + n0;
        #pragma unroll
        for (int ni = 0; ni < 4; ni++) {
            const int n = tx * 4 + ni;
            orow[n] = acc[mi][ni] + bo[n0 + n];
        }
    }
}

// ---------------------------------------------------------------------------
extern "C" void kernel_launch(void* const* d_in, const int* in_sizes, int n_in,
                              void* d_out, int out_size)
{
    const float* x    = (const float*)d_in[0];
    const float* W1   = (const float*)d_in[1];
    const float* b1   = (const float*)d_in[2];
    const float* W2   = (const float*)d_in[3];
    const float* b2   = (const float*)d_in[4];
    const float* ln_s = (const float*)d_in[5];
    const float* ln_b = (const float*)d_in[6];
    const float* Wp   = (const float*)d_in[7];
    const float* bp   = (const float*)d_in[8];
    const float* Wo   = (const float*)d_in[9];
    const float* bo   = (const float*)d_in[10];
    float* out = (float*)d_out;

    cudaFuncSetAttribute(pair_mma_kernel, cudaFuncAttributeMaxDynamicSharedMemorySize, PAIR_SMEM);

    senet_a1_kernel<<<Bn / 8, 256>>>(x, W1, b1);
    senet_ln_kernel<<<Bn / 8, 256>>>(x, W2, b2, ln_s, ln_b, out);
    pair_mma_kernel<<<dim3(Pn, Bn / 128), 256, PAIR_SMEM>>>(x, Wp, bp);
    outgemm_kernel<<<dim3(OUTN / 64, Bn / 64), 256>>>(Wo, bo, out);
}